// round 4
// baseline (speedup 1.0000x reference)
#include <cuda_runtime.h>
#include <math_constants.h>

// Shapes: V=1024 fixed; B,L,T from in_sizes. Scratch for B<=64, T<=1016, S<=256.
#define VOCAB      1024
#define MAXB       64
#define MAXTP      1032          // padded T rows (T + 8 prefetch slack)
#define SP         256           // padded extended-state stride (>= S = 2L+1), 8 per lane
#define P1_THREADS 128
#define WPB        8             // warps (=batches) per CTA in pass 2
#define FULLMASK   0xffffffffu

#define LOG2E_F 1.4426950408889634f
#define LN2_F   0.6931471805599453f

static __device__ __forceinline__ float fex2(float x) {
    float y; asm("ex2.approx.f32 %0, %1;" : "=f"(y) : "f"(x)); return y;
}

// Scratch: per-(b,t) extended-label PROBABILITIES (softmax, gathered), padded.
__device__ float g_p[(size_t)MAXB * MAXTP * SP];
__device__ float g_loss[MAXB];

// ---------------------------------------------------------------------------
// Pass 1: per-row softmax + gather of the S extended-label probs into compact
// scratch (prob domain). One CTA of 128 threads per (b,t) row.
// Register-resident row (8 floats/thread); gather reads labels from L1.
// ---------------------------------------------------------------------------
__global__ void __launch_bounds__(P1_THREADS)
softmax_gather_kernel(const float* __restrict__ pred,
                      const int*   __restrict__ gt,
                      int T, int TP, int L, int S)
{
    __shared__ float sred[8];     // [0..3] warp maxes, [4..7] warp sums

    const int row = blockIdx.x;           // b*T + t
    const int b   = row / T;
    const int tid = threadIdx.x;
    const int lane = tid & 31, wid = tid >> 5;

    const float* __restrict__ p = pred + (size_t)row * VOCAB;

    // Load 8 values/thread into registers, tracking max.
    float4 v0 = *reinterpret_cast<const float4*>(p + tid * 4);
    float4 v1 = *reinterpret_cast<const float4*>(p + tid * 4 + 512);
    float lmax = fmaxf(fmaxf(fmaxf(v0.x, v0.y), fmaxf(v0.z, v0.w)),
                       fmaxf(fmaxf(v1.x, v1.y), fmaxf(v1.z, v1.w)));
    #pragma unroll
    for (int o = 16; o; o >>= 1)
        lmax = fmaxf(lmax, __shfl_xor_sync(FULLMASK, lmax, o));
    if (lane == 0) sred[wid] = lmax;
    __syncthreads();
    const float bm = fmaxf(fmaxf(sred[0], sred[1]), fmaxf(sred[2], sred[3]));
    const float c  = bm * LOG2E_F;

    // Sum of exp2(x*log2e - c) from registers.
    float lsum = fex2(fmaf(v0.x, LOG2E_F, -c)) + fex2(fmaf(v0.y, LOG2E_F, -c))
               + fex2(fmaf(v0.z, LOG2E_F, -c)) + fex2(fmaf(v0.w, LOG2E_F, -c))
               + fex2(fmaf(v1.x, LOG2E_F, -c)) + fex2(fmaf(v1.y, LOG2E_F, -c))
               + fex2(fmaf(v1.z, LOG2E_F, -c)) + fex2(fmaf(v1.w, LOG2E_F, -c));
    #pragma unroll
    for (int o = 16; o; o >>= 1)
        lsum += __shfl_xor_sync(FULLMASK, lsum, o);
    if (lane == 0) sred[4 + wid] = lsum;   // disjoint slots: no extra barrier
    __syncthreads();
    const float bs     = sred[4] + sred[5] + sred[6] + sred[7];
    const float inv_bs = __frcp_rn(bs);

    // Gather extended labels as probabilities; pad states get exact 0.
    const int t = row - b * T;
    float* __restrict__ out = g_p + ((size_t)b * TP + t) * SP;
    const int* __restrict__ gtb = gt + (size_t)b * L;
    #pragma unroll
    for (int k = 0; k < SP / P1_THREADS; k++) {
        int s = tid + k * P1_THREADS;
        float v = 0.f;
        if (s < S) {
            int lab = 0;
            if (s & 1) {
                int idx = (s >> 1); if (idx > L - 1) idx = L - 1;
                lab = gtb[idx];
            }
            v = fex2(fmaf(__ldg(p + lab), LOG2E_F, -c)) * inv_bs;
        }
        out[s] = v;
    }
}

// ---------------------------------------------------------------------------
// Pass 2: CTC forward recursion, prob domain with PER-LANE block floating
// point. One WARP per batch, 8 warps per CTA (warps w and w+4 share an SMSP,
// interleaving issue to hide the rt=2 FMA floor and SHFL latency).
// Lane l owns states [8l, 8l+8) with its own int exponent El. Cross-lane
// terms scaled by exact f = 2^(El_left - El), refreshed at each renorm
// (every 4 steps; adoption pacing requires renorm-4).
// ---------------------------------------------------------------------------
__global__ void __launch_bounds__(WPB * 32)
ctc_forward_kernel(const int* __restrict__ plen,
                   const int* __restrict__ gt,
                   const int* __restrict__ gtl,
                   int B, int T, int TP, int L, int S)
{
    const int w    = threadIdx.x >> 5;
    const int b    = blockIdx.x * WPB + w;
    if (b >= B) return;
    const int lane = threadIdx.x & 31;
    const int ilen = min(plen[b], T);
    const int tl   = gtl[b];
    const float* __restrict__ Pb = g_p + (size_t)b * TP * SP + lane * 8;
    const int* __restrict__ gtb = gt + (size_t)b * L;

    // Static skip masks (1.0f where the 2-step transition is allowed)
    float m[8];
    #pragma unroll
    for (int j = 0; j < 8; j++) {
        int s = lane * 8 + j;
        float mm = 0.f;
        if (s >= 2 && (s & 1) && s < S) {
            int lab = gtb[s >> 1], lm2 = gtb[(s >> 1) - 1];
            mm = (lab != 0 && lab != lm2) ? 1.f : 0.f;
        }
        m[j] = mm;
    }

    // alpha(t=0)
    float a[8];
    #pragma unroll
    for (int j = 0; j < 8; j++) a[j] = 0.f;
    if (lane == 0) {
        float4 q0 = *reinterpret_cast<const float4*>(Pb);
        a[0] = q0.x;
        a[1] = (tl > 0) ? q0.y : 0.f;
    }

    int   El = 0;                          // per-lane exponent
    float f  = (lane == 0) ? 0.f : 1.f;    // 2^(El_left - El); lane 0 has no left
    const int nsteps = ilen - 1;           // recursion runs t = 1 .. ilen-1

#define CTC_STEP(Q0, Q1)                                                    \
    do {                                                                     \
        float u7 = __shfl_up_sync(FULLMASK, a[7], 1) * f;                    \
        float u6 = __shfl_up_sync(FULLMASK, a[6], 1) * f;                    \
        float n0 = fmaf(m[0], u6,   a[0] + u7)   * (Q0).x;                   \
        float n1 = fmaf(m[1], u7,   a[1] + a[0]) * (Q0).y;                   \
        float n2 = fmaf(m[2], a[0], a[2] + a[1]) * (Q0).z;                   \
        float n3 = fmaf(m[3], a[1], a[3] + a[2]) * (Q0).w;                   \
        float n4 = fmaf(m[4], a[2], a[4] + a[3]) * (Q1).x;                   \
        float n5 = fmaf(m[5], a[3], a[5] + a[4]) * (Q1).y;                   \
        float n6 = fmaf(m[6], a[4], a[6] + a[5]) * (Q1).z;                   \
        float n7 = fmaf(m[7], a[5], a[7] + a[6]) * (Q1).w;                   \
        a[0]=n0; a[1]=n1; a[2]=n2; a[3]=n3; a[4]=n4; a[5]=n5; a[6]=n6; a[7]=n7; \
    } while (0)

#define CTC_RENORM()                                                        \
    do {                                                                     \
        float mx = fmaxf(fmaxf(fmaxf(a[0], a[1]), fmaxf(a[2], a[3])),       \
                         fmaxf(fmaxf(a[4], a[5]), fmaxf(a[6], a[7])));       \
        bool nz = (mx > 0.f);                                                \
        int  e  = nz ? ((__float_as_int(mx) >> 23) - 127) : 0;               \
        int  Elp = El + e;                                                   \
        int  Eleft = __shfl_up_sync(FULLMASK, Elp, 1);                       \
        if (!nz && lane > 0) Elp = Eleft;      /* adopt neighbor's scale */  \
        if (nz) {                                                            \
            float sc = __int_as_float((127 - e) << 23);                      \
            _Pragma("unroll")                                                \
            for (int j = 0; j < 8; j++) a[j] *= sc;                          \
        }                                                                    \
        El = Elp;                                                            \
        int El2 = __shfl_up_sync(FULLMASK, El, 1);                           \
        int dE  = El2 - El;                                                  \
        if (lane == 0 || dE < -126) f = 0.f;                                 \
        else f = __int_as_float((min(dE, 126) + 127) << 23);                 \
    } while (0)

    // Prefetch pipeline, depth 8. Scratch is padded to TP >= T+8 rows, so no
    // bounds clamp is needed; rows beyond nsteps are loaded but never consumed.
    const float* ptr = Pb + (size_t)SP;    // row t = 1
    float4 pf0[8], pf1[8];
    #pragma unroll
    for (int k = 0; k < 8; k++) {
        pf0[k] = *reinterpret_cast<const float4*>(ptr + (size_t)k * SP);
        pf1[k] = *reinterpret_cast<const float4*>(ptr + (size_t)k * SP + 4);
    }

    int t = 1;
    for (; t + 7 <= nsteps; t += 8) {
        #pragma unroll
        for (int k = 0; k < 8; k++) {
            float4 q0 = pf0[k], q1 = pf1[k];
            pf0[k] = *reinterpret_cast<const float4*>(ptr + (size_t)(k + 8) * SP);
            pf1[k] = *reinterpret_cast<const float4*>(ptr + (size_t)(k + 8) * SP + 4);
            CTC_STEP(q0, q1);
            if (k == 3 || k == 7) CTC_RENORM();
        }
        ptr += 8 * SP;
    }
    for (; t <= nsteps; t++) {
        float4 q0 = *reinterpret_cast<const float4*>(Pb + (size_t)t * SP);
        float4 q1 = *reinterpret_cast<const float4*>(Pb + (size_t)t * SP + 4);
        CTC_STEP(q0, q1);
    }
#undef CTC_STEP
#undef CTC_RENORM

    // end_ll over alpha[2*tl] and alpha[max(2*tl-1,0)]
    int s1 = 2 * tl;
    int s2 = (2 * tl - 1 > 0) ? (2 * tl - 1) : 0;
    int lane1 = s1 >> 3, slot1 = s1 & 7;
    int lane2 = s2 >> 3, slot2 = s2 & 7;
    float v1 = a[0], v2 = a[0];
    #pragma unroll
    for (int j = 1; j < 8; j++) { v1 = (slot1 == j) ? a[j] : v1;
                                  v2 = (slot2 == j) ? a[j] : v2; }
    int   E1 = __shfl_sync(FULLMASK, El, lane1);
    int   E2 = __shfl_sync(FULLMASK, El, lane2);
    v1 = __shfl_sync(FULLMASK, v1, lane1);
    v2 = __shfl_sync(FULLMASK, v2, lane2);

    if (lane == 0) {
        float l1 = (v1 > 0.f) ? (log2f(v1) + (float)E1) : -3.0e38f;
        float l2 = (v2 > 0.f) ? (log2f(v2) + (float)E2) : -3.0e38f;
        float mm = fmaxf(l1, l2);
        float loss;
        if (mm < -2.0e38f) {
            loss = 0.f;                    // zero_infinity: p == 0
        } else {
            float tot2 = mm + log2f(exp2f(l1 - mm) + exp2f(l2 - mm));
            loss = -tot2 * LN2_F;
        }
        g_loss[b] = loss / (float)tl;
    }
}

// ---------------------------------------------------------------------------
// Pass 3: deterministic batch-mean reduction (single warp).
// ---------------------------------------------------------------------------
__global__ void reduce_loss_kernel(float* __restrict__ out, int B)
{
    float v = 0.f;
    for (int i = threadIdx.x; i < B; i += 32) v += g_loss[i];
    #pragma unroll
    for (int o = 16; o; o >>= 1) v += __shfl_xor_sync(FULLMASK, v, o);
    if (threadIdx.x == 0) out[0] = v / (float)B;
}

// ---------------------------------------------------------------------------
extern "C" void kernel_launch(void* const* d_in, const int* in_sizes, int n_in,
                              void* d_out, int out_size)
{
    const float* pred = (const float*)d_in[0];
    const int*   plen = (const int*)d_in[1];
    const int*   gt   = (const int*)d_in[2];
    const int*   gtl  = (const int*)d_in[3];

    const int B  = in_sizes[1];
    const int L  = in_sizes[2] / B;
    const int T  = in_sizes[0] / (B * VOCAB);
    const int S  = 2 * L + 1;
    const int TP = T + 8;                 // padded rows (prefetch slack)

    softmax_gather_kernel<<<B * T, P1_THREADS>>>(pred, gt, T, TP, L, S);
    ctc_forward_kernel<<<(B + WPB - 1) / WPB, WPB * 32>>>(plen, gt, gtl, B, T, TP, L, S);
    reduce_loss_kernel<<<1, 32>>>((float*)d_out, B);
}

// round 6
// speedup vs baseline: 1.6617x; 1.6617x over previous
#include <cuda_runtime.h>
#include <math_constants.h>
#include <cstdint>

// Shapes: V=1024 fixed; B,L,T from in_sizes. Scratch for B<=64, T<=1024, S<=256.
#define VOCAB      1024
#define MAXB       64
#define MAXTP      1056          // padded T rows (T + 32 prefetch slack)
#define SP         256           // padded extended-state stride (>= S = 2L+1), 8 per lane
#define P1_THREADS 128
#define RING       32            // smem ring slots (rows) per warp
#define DIST       28            // prefetch distance (rows ahead)
#define FULLMASK   0xffffffffu

#define LOG2E_F 1.4426950408889634f
#define LN2_F   0.6931471805599453f

static __device__ __forceinline__ float fex2(float x) {
    float y; asm("ex2.approx.f32 %0, %1;" : "=f"(y) : "f"(x)); return y;
}

#define CP16(sm, gp) \
    asm volatile("cp.async.cg.shared.global [%0], [%1], 16;" :: "r"(sm), "l"(gp))
#define CP_COMMIT() \
    asm volatile("cp.async.commit_group;" ::: "memory")
#define CP_WAIT_26() \
    asm volatile("cp.async.wait_group 26;" ::: "memory")
#define CP_WAIT_27() \
    asm volatile("cp.async.wait_group 27;" ::: "memory")

// Scratch: per-(b,t) extended-label PROBABILITIES (softmax, gathered), padded.
__device__ float g_p[(size_t)MAXB * MAXTP * SP];
__device__ float g_loss[MAXB];

// ---------------------------------------------------------------------------
// Pass 1: per-row softmax + gather of the S extended-label probs into compact
// scratch (prob domain). One CTA of 128 threads per (b,t) row.
// ---------------------------------------------------------------------------
__global__ void __launch_bounds__(P1_THREADS)
softmax_gather_kernel(const float* __restrict__ pred,
                      const int*   __restrict__ gt,
                      int T, int TP, int L, int S)
{
    __shared__ float sred[8];     // [0..3] warp maxes, [4..7] warp sums

    const int row = blockIdx.x;           // b*T + t
    const int b   = row / T;
    const int tid = threadIdx.x;
    const int lane = tid & 31, wid = tid >> 5;

    const float* __restrict__ p = pred + (size_t)row * VOCAB;

    float4 v0 = *reinterpret_cast<const float4*>(p + tid * 4);
    float4 v1 = *reinterpret_cast<const float4*>(p + tid * 4 + 512);
    float lmax = fmaxf(fmaxf(fmaxf(v0.x, v0.y), fmaxf(v0.z, v0.w)),
                       fmaxf(fmaxf(v1.x, v1.y), fmaxf(v1.z, v1.w)));
    #pragma unroll
    for (int o = 16; o; o >>= 1)
        lmax = fmaxf(lmax, __shfl_xor_sync(FULLMASK, lmax, o));
    if (lane == 0) sred[wid] = lmax;
    __syncthreads();
    const float bm = fmaxf(fmaxf(sred[0], sred[1]), fmaxf(sred[2], sred[3]));
    const float c  = bm * LOG2E_F;

    float lsum = fex2(fmaf(v0.x, LOG2E_F, -c)) + fex2(fmaf(v0.y, LOG2E_F, -c))
               + fex2(fmaf(v0.z, LOG2E_F, -c)) + fex2(fmaf(v0.w, LOG2E_F, -c))
               + fex2(fmaf(v1.x, LOG2E_F, -c)) + fex2(fmaf(v1.y, LOG2E_F, -c))
               + fex2(fmaf(v1.z, LOG2E_F, -c)) + fex2(fmaf(v1.w, LOG2E_F, -c));
    #pragma unroll
    for (int o = 16; o; o >>= 1)
        lsum += __shfl_xor_sync(FULLMASK, lsum, o);
    if (lane == 0) sred[4 + wid] = lsum;
    __syncthreads();
    const float bs     = sred[4] + sred[5] + sred[6] + sred[7];
    const float inv_bs = __frcp_rn(bs);

    const int t = row - b * T;
    float* __restrict__ out = g_p + ((size_t)b * TP + t) * SP;
    const int* __restrict__ gtb = gt + (size_t)b * L;
    #pragma unroll
    for (int k = 0; k < SP / P1_THREADS; k++) {
        int s = tid + k * P1_THREADS;
        float v = 0.f;
        if (s < S) {
            int lab = 0;
            if (s & 1) {
                int idx = (s >> 1); if (idx > L - 1) idx = L - 1;
                lab = gtb[idx];
            }
            v = fex2(fmaf(__ldg(p + lab), LOG2E_F, -c)) * inv_bs;
        }
        out[s] = v;
    }
}

// ---------------------------------------------------------------------------
// Pass 2: CTC forward recursion, prob domain with PER-LANE block floating
// point (renorm every 4 steps — proven numerics). One warp per CTA/batch.
// The per-step p-row (1KB) flows through a 32-slot SMEM ring filled by
// cp.async at distance 28, covering DRAM latency (g_p gets evicted from L2
// by pass 1's 131MB pred stream). Each lane copies and re-reads its own
// 32B, so no intra-warp sync is needed.
// ---------------------------------------------------------------------------
__global__ void __launch_bounds__(32)
ctc_forward_kernel(const int* __restrict__ plen,
                   const int* __restrict__ gt,
                   const int* __restrict__ gtl,
                   int B, int T, int TP, int L, int S)
{
    __shared__ float ring[RING][SP];     // 32 KB

    const int b    = blockIdx.x;
    const int lane = threadIdx.x;
    const int ilen = min(plen[b], T);
    const int tl   = gtl[b];
    const float* __restrict__ Pb = g_p + (size_t)b * TP * SP + lane * 8;
    const int* __restrict__ gtb = gt + (size_t)b * L;
    const unsigned int rb =
        (unsigned int)__cvta_generic_to_shared(ring) + (unsigned int)(lane * 32);

    // Static skip masks (1.0f where the 2-step transition is allowed)
    float m[8];
    #pragma unroll
    for (int j = 0; j < 8; j++) {
        int s = lane * 8 + j;
        float mm = 0.f;
        if (s >= 2 && (s & 1) && s < S) {
            int lab = gtb[s >> 1], lm2 = gtb[(s >> 1) - 1];
            mm = (lab != 0 && lab != lm2) ? 1.f : 0.f;
        }
        m[j] = mm;
    }

    // alpha(t=0)
    float a[8];
    #pragma unroll
    for (int j = 0; j < 8; j++) a[j] = 0.f;
    if (lane == 0) {
        float4 q = *reinterpret_cast<const float4*>(Pb);
        a[0] = q.x;
        a[1] = (tl > 0) ? q.y : 0.f;
    }

    int   El = 0;                          // per-lane exponent
    float f  = (lane == 0) ? 0.f : 1.f;    // 2^(El_left - El); lane 0 has no left
    const int nsteps = ilen - 1;           // recursion runs t = 1 .. ilen-1

#define CTC_STEP(Q0, Q1)                                                    \
    do {                                                                     \
        float u7 = __shfl_up_sync(FULLMASK, a[7], 1) * f;                    \
        float u6 = __shfl_up_sync(FULLMASK, a[6], 1) * f;                    \
        float n0 = fmaf(m[0], u6,   a[0] + u7)   * (Q0).x;                   \
        float n1 = fmaf(m[1], u7,   a[1] + a[0]) * (Q0).y;                   \
        float n2 = fmaf(m[2], a[0], a[2] + a[1]) * (Q0).z;                   \
        float n3 = fmaf(m[3], a[1], a[3] + a[2]) * (Q0).w;                   \
        float n4 = fmaf(m[4], a[2], a[4] + a[3]) * (Q1).x;                   \
        float n5 = fmaf(m[5], a[3], a[5] + a[4]) * (Q1).y;                   \
        float n6 = fmaf(m[6], a[4], a[6] + a[5]) * (Q1).z;                   \
        float n7 = fmaf(m[7], a[5], a[7] + a[6]) * (Q1).w;                   \
        a[0]=n0; a[1]=n1; a[2]=n2; a[3]=n3; a[4]=n4; a[5]=n5; a[6]=n6; a[7]=n7; \
    } while (0)

#define CTC_RENORM()                                                        \
    do {                                                                     \
        float mx = fmaxf(fmaxf(fmaxf(a[0], a[1]), fmaxf(a[2], a[3])),       \
                         fmaxf(fmaxf(a[4], a[5]), fmaxf(a[6], a[7])));       \
        bool nz = (mx > 0.f);                                                \
        int  e  = nz ? ((__float_as_int(mx) >> 23) - 127) : 0;               \
        int  Elp = El + e;                                                   \
        int  Eleft = __shfl_up_sync(FULLMASK, Elp, 1);                       \
        if (!nz && lane > 0) Elp = Eleft;      /* adopt neighbor's scale */  \
        if (nz) {                                                            \
            float sc = __int_as_float((127 - e) << 23);                      \
            _Pragma("unroll")                                                \
            for (int j = 0; j < 8; j++) a[j] *= sc;                          \
        }                                                                    \
        El = Elp;                                                            \
        int El2 = __shfl_up_sync(FULLMASK, El, 1);                           \
        int dE  = El2 - El;                                                  \
        if (lane == 0 || dE < -126) f = 0.f;                                 \
        else f = __int_as_float((min(dE, 126) + 127) << 23);                 \
    } while (0)

    // Prologue: fill ring with rows 1..DIST (pad rows may contain garbage;
    // they are copied but never consumed past nsteps).
    {
        const float* gp = Pb + SP;           // row 1
        #pragma unroll 4
        for (int r = 1; r <= DIST; r++) {
            unsigned int sa = rb + (unsigned int)((r & (RING - 1)) * (SP * 4));
            CP16(sa, gp); CP16(sa + 16, gp + 4);
            CP_COMMIT();
            gp += SP;
        }
    }

    float4 q0 = make_float4(0.f, 0.f, 0.f, 0.f), q1 = q0;
    if (nsteps >= 1) {
        CP_WAIT_27();                        // row 1 landed
        const float4* sp = reinterpret_cast<const float4*>(&ring[1][lane * 8]);
        q0 = sp[0]; q1 = sp[1];
    }

    const float* fill_ptr = Pb + (size_t)(1 + DIST) * SP;
    int t = 1;
    for (; t + 7 <= nsteps; t += 8) {
        #pragma unroll
        for (int k = 0; k < 8; k++) {
            CP_WAIT_26();                    // row t+k+1 landed
            int nslot = (t + k + 1) & (RING - 1);
            const float4* sp = reinterpret_cast<const float4*>(&ring[nslot][lane * 8]);
            float4 nq0 = sp[0], nq1 = sp[1];
            // refill: row t+k+DIST into its slot
            {
                unsigned int sa = rb +
                    (unsigned int)((((t + k + DIST) & (RING - 1))) * (SP * 4));
                const float* gp = fill_ptr + (size_t)k * SP;
                CP16(sa, gp); CP16(sa + 16, gp + 4);
                CP_COMMIT();
            }
            CTC_STEP(q0, q1);
            if (k == 3 || k == 7) CTC_RENORM();
            q0 = nq0; q1 = nq1;
        }
        fill_ptr += 8 * SP;
    }
    for (; t <= nsteps; t++) {
        CTC_STEP(q0, q1);
        if (t + 1 <= nsteps) {
            q0 = *reinterpret_cast<const float4*>(Pb + (size_t)(t + 1) * SP);
            q1 = *reinterpret_cast<const float4*>(Pb + (size_t)(t + 1) * SP + 4);
        }
    }
#undef CTC_STEP
#undef CTC_RENORM

    // end_ll over alpha[2*tl] and alpha[max(2*tl-1,0)]
    int s1 = 2 * tl;
    int s2 = (2 * tl - 1 > 0) ? (2 * tl - 1) : 0;
    int lane1 = s1 >> 3, slot1 = s1 & 7;
    int lane2 = s2 >> 3, slot2 = s2 & 7;
    float v1 = a[0], v2 = a[0];
    #pragma unroll
    for (int j = 1; j < 8; j++) { v1 = (slot1 == j) ? a[j] : v1;
                                  v2 = (slot2 == j) ? a[j] : v2; }
    int   E1 = __shfl_sync(FULLMASK, El, lane1);
    int   E2 = __shfl_sync(FULLMASK, El, lane2);
    v1 = __shfl_sync(FULLMASK, v1, lane1);
    v2 = __shfl_sync(FULLMASK, v2, lane2);

    if (lane == 0) {
        float l1 = (v1 > 0.f) ? (log2f(v1) + (float)E1) : -3.0e38f;
        float l2 = (v2 > 0.f) ? (log2f(v2) + (float)E2) : -3.0e38f;
        float mm = fmaxf(l1, l2);
        float loss;
        if (mm < -2.0e38f) {
            loss = 0.f;                    // zero_infinity: p == 0
        } else {
            float tot2 = mm + log2f(exp2f(l1 - mm) + exp2f(l2 - mm));
            loss = -tot2 * LN2_F;
        }
        g_loss[b] = loss / (float)tl;
    }
}

// ---------------------------------------------------------------------------
// Pass 3: deterministic batch-mean reduction (single warp).
// ---------------------------------------------------------------------------
__global__ void reduce_loss_kernel(float* __restrict__ out, int B)
{
    float v = 0.f;
    for (int i = threadIdx.x; i < B; i += 32) v += g_loss[i];
    #pragma unroll
    for (int o = 16; o; o >>= 1) v += __shfl_xor_sync(FULLMASK, v, o);
    if (threadIdx.x == 0) out[0] = v / (float)B;
}

// ---------------------------------------------------------------------------
extern "C" void kernel_launch(void* const* d_in, const int* in_sizes, int n_in,
                              void* d_out, int out_size)
{
    const float* pred = (const float*)d_in[0];
    const int*   plen = (const int*)d_in[1];
    const int*   gt   = (const int*)d_in[2];
    const int*   gtl  = (const int*)d_in[3];

    const int B  = in_sizes[1];
    const int L  = in_sizes[2] / B;
    const int T  = in_sizes[0] / (B * VOCAB);
    const int S  = 2 * L + 1;
    const int TP = T + 32;                // padded rows (prefetch slack)

    softmax_gather_kernel<<<B * T, P1_THREADS>>>(pred, gt, T, TP, L, S);
    ctc_forward_kernel<<<B, 32>>>(plen, gt, gtl, B, T, TP, L, S);
    reduce_loss_kernel<<<1, 32>>>((float*)d_out, B);
}

// round 7
// speedup vs baseline: 1.6630x; 1.0007x over previous
#include <cuda_runtime.h>
#include <math_constants.h>
#include <cstdint>

// Shapes: V=1024 fixed; B,L,T from in_sizes. Scratch for B<=64, T<=1024, S<=256.
#define VOCAB      1024
#define MAXB       64
#define MAXTP      1056          // padded T rows (T + 32 prefetch slack)
#define SP         256           // padded extended-state stride (>= S = 2L+1), 8 per lane
#define RING       32            // smem ring slots (rows) per warp
#define DIST       28            // prefetch distance (rows ahead)
#define FULLMASK   0xffffffffu

#define LOG2E_F 1.4426950408889634f
#define LN2_F   0.6931471805599453f

typedef unsigned long long ull;

static __device__ __forceinline__ float fex2(float x) {
    float y; asm("ex2.approx.f32 %0, %1;" : "=f"(y) : "f"(x)); return y;
}

// packed f32x2 helpers (sm_103a FFMA2 path)
#define PK(v,l,h)     asm("mov.b64 %0, {%1, %2};" : "=l"(v) : "f"(l), "f"(h))
#define UNPK(l,h,v)   asm("mov.b64 {%0, %1}, %2;" : "=f"(l), "=f"(h) : "l"(v))
#define ADD2(d,a,b)   asm("add.rn.f32x2 %0, %1, %2;" : "=l"(d) : "l"(a), "l"(b))
#define MUL2(d,a,b)   asm("mul.rn.f32x2 %0, %1, %2;" : "=l"(d) : "l"(a), "l"(b))
#define FMA2(d,a,b,c) asm("fma.rn.f32x2 %0, %1, %2, %3;" : "=l"(d) : "l"(a), "l"(b), "l"(c))

#define CP16(sm, gp) \
    asm volatile("cp.async.cg.shared.global [%0], [%1], 16;" :: "r"(sm), "l"(gp))
#define CP_COMMIT() \
    asm volatile("cp.async.commit_group;" ::: "memory")
#define CP_WAIT_26() \
    asm volatile("cp.async.wait_group 26;" ::: "memory")
#define CP_WAIT_27() \
    asm volatile("cp.async.wait_group 27;" ::: "memory")
#define CP_WAIT_ALL() \
    asm volatile("cp.async.wait_all;" ::: "memory")

// Scratch: per-(b,t) extended-label PROBABILITIES (softmax, gathered), padded.
__device__ float g_p[(size_t)MAXB * MAXTP * SP];
__device__ float g_loss[MAXB];

// ---------------------------------------------------------------------------
// Pass 1: per-row softmax + gather. ONE WARP PER ROW (32 values/lane in
// registers, MLP=8), no SMEM, no CTA barriers. 8 rows per 256-thread CTA.
// ---------------------------------------------------------------------------
__global__ void __launch_bounds__(256)
softmax_gather_kernel(const float* __restrict__ pred,
                      const int*   __restrict__ gt,
                      int NT, int T, int TP, int L, int S)
{
    const int row  = blockIdx.x * 8 + (threadIdx.x >> 5);
    if (row >= NT) return;
    const int lane = threadIdx.x & 31;
    const int b    = row / T;
    const int t    = row - b * T;

    const float* __restrict__ p = pred + (size_t)row * VOCAB;

    // 8 x float4 per lane (coalesced, MLP 8)
    float4 v[8];
    #pragma unroll
    for (int k = 0; k < 8; k++)
        v[k] = *reinterpret_cast<const float4*>(p + lane * 4 + k * 128);

    float mx = -CUDART_INF_F;
    #pragma unroll
    for (int k = 0; k < 8; k++)
        mx = fmaxf(mx, fmaxf(fmaxf(v[k].x, v[k].y), fmaxf(v[k].z, v[k].w)));
    #pragma unroll
    for (int o = 16; o; o >>= 1)
        mx = fmaxf(mx, __shfl_xor_sync(FULLMASK, mx, o));
    const float c = mx * LOG2E_F;

    float sum = 0.f;
    #pragma unroll
    for (int k = 0; k < 8; k++) {
        sum += fex2(fmaf(v[k].x, LOG2E_F, -c)) + fex2(fmaf(v[k].y, LOG2E_F, -c))
             + fex2(fmaf(v[k].z, LOG2E_F, -c)) + fex2(fmaf(v[k].w, LOG2E_F, -c));
    }
    #pragma unroll
    for (int o = 16; o; o >>= 1)
        sum += __shfl_xor_sync(FULLMASK, sum, o);
    const float inv = __frcp_rn(sum);

    // Gather extended labels as probabilities; pad states get exact 0.
    float* __restrict__ out = g_p + ((size_t)b * TP + t) * SP;
    const int* __restrict__ gtb = gt + (size_t)b * L;
    float val[8];
    #pragma unroll
    for (int j = 0; j < 8; j++) {
        int s = lane * 8 + j;
        float r = 0.f;
        if (s < S) {
            int lab = 0;
            if (s & 1) {
                int idx = (s >> 1); if (idx > L - 1) idx = L - 1;
                lab = gtb[idx];
            }
            r = fex2(fmaf(__ldg(p + lab), LOG2E_F, -c)) * inv;
        }
        val[j] = r;
    }
    *reinterpret_cast<float4*>(out + lane * 8)     = make_float4(val[0], val[1], val[2], val[3]);
    *reinterpret_cast<float4*>(out + lane * 8 + 4) = make_float4(val[4], val[5], val[6], val[7]);
}

// ---------------------------------------------------------------------------
// Pass 2: CTC forward recursion, prob domain, PER-LANE block floating point
// (renorm every 4 steps — proven numerics), f32x2-PACKED math: 4 b64 regs
// hold 8 states/lane; add/fma/mul.rn.f32x2 halve FMA-pipe ops, mov.b64
// re-packs ride the ALU pipe. cp.async SMEM ring (depth 28) hides DRAM.
// One warp per CTA/batch.
// ---------------------------------------------------------------------------
__global__ void __launch_bounds__(32)
ctc_forward_kernel(const int* __restrict__ plen,
                   const int* __restrict__ gt,
                   const int* __restrict__ gtl,
                   int B, int T, int TP, int L, int S)
{
    __shared__ float ring[RING][SP];     // 32 KB

    const int b    = blockIdx.x;
    const int lane = threadIdx.x;
    const int ilen = min(plen[b], T);
    const int tl   = gtl[b];
    const float* __restrict__ Pb = g_p + (size_t)b * TP * SP + lane * 8;
    const int* __restrict__ gtb = gt + (size_t)b * L;
    const unsigned int rb =
        (unsigned int)__cvta_generic_to_shared(ring) + (unsigned int)(lane * 32);

    // Static skip masks, packed in pairs
    float mm[8];
    #pragma unroll
    for (int j = 0; j < 8; j++) {
        int s = lane * 8 + j;
        float v = 0.f;
        if (s >= 2 && (s & 1) && s < S) {
            int lab = gtb[s >> 1], lm2 = gtb[(s >> 1) - 1];
            v = (lab != 0 && lab != lm2) ? 1.f : 0.f;
        }
        mm[j] = v;
    }
    ull M0, M1, M2, M3;
    PK(M0, mm[0], mm[1]); PK(M1, mm[2], mm[3]);
    PK(M2, mm[4], mm[5]); PK(M3, mm[6], mm[7]);

    // alpha(t=0), packed
    float i0 = 0.f, i1 = 0.f;
    if (lane == 0) {
        float4 q = *reinterpret_cast<const float4*>(Pb);
        i0 = q.x;
        i1 = (tl > 0) ? q.y : 0.f;
    }
    ull A0, A1, A2, A3, ZERO;
    PK(ZERO, 0.f, 0.f);
    PK(A0, i0, i1);
    A1 = ZERO; A2 = ZERO; A3 = ZERO;

    int   El = 0;                          // per-lane exponent
    float f  = (lane == 0) ? 0.f : 1.f;    // 2^(El_left - El); lane 0 has no left
    const int nsteps = ilen - 1;           // recursion runs t = 1 .. ilen-1

#define CTC_STEP(Q0, Q1, Q2, Q3)                                            \
    do {                                                                     \
        float x0,y0,x1,y1,x2,y2,x3,y3;                                       \
        UNPK(x3, y3, A3);                                                    \
        float u7 = __shfl_up_sync(FULLMASK, y3, 1);                          \
        float u6 = __shfl_up_sync(FULLMASK, x3, 1);                          \
        UNPK(x0, y0, A0); UNPK(x1, y1, A1); UNPK(x2, y2, A2);                \
        float u7f = u7 * f, u6f = u6 * f;                                    \
        ull P10, P20, P11, P12, P13;                                         \
        PK(P20, u6f, u7f); PK(P10, u7f, x0);                                 \
        PK(P11, y0, x1); PK(P12, y1, x2); PK(P13, y2, x3);                   \
        ull T0, T1, T2, T3;                                                  \
        ADD2(T0, A0, P10); ADD2(T1, A1, P11);                                \
        ADD2(T2, A2, P12); ADD2(T3, A3, P13);                                \
        FMA2(T0, M0, P20, T0); FMA2(T1, M1, A0, T1);                         \
        FMA2(T2, M2, A1, T2);  FMA2(T3, M3, A2, T3);                         \
        MUL2(A3, T3, Q3); MUL2(A2, T2, Q2);                                  \
        MUL2(A1, T1, Q1); MUL2(A0, T0, Q0);                                  \
    } while (0)

#define CTC_RENORM()                                                        \
    do {                                                                     \
        float x0,y0,x1,y1,x2,y2,x3,y3;                                       \
        UNPK(x0, y0, A0); UNPK(x1, y1, A1);                                  \
        UNPK(x2, y2, A2); UNPK(x3, y3, A3);                                  \
        float mx = fmaxf(fmaxf(fmaxf(x0, y0), fmaxf(x1, y1)),                \
                         fmaxf(fmaxf(x2, y2), fmaxf(x3, y3)));               \
        bool nz = (mx > 0.f);                                                \
        int  e  = nz ? ((__float_as_int(mx) >> 23) - 127) : 0;               \
        int  Elp = El + e;                                                   \
        int  Eleft = __shfl_up_sync(FULLMASK, Elp, 1);                       \
        if (!nz && lane > 0) Elp = Eleft;      /* adopt neighbor's scale */  \
        if (nz) {                                                            \
            float sc = __int_as_float((127 - e) << 23);                      \
            ull SC; PK(SC, sc, sc);                                          \
            MUL2(A0, A0, SC); MUL2(A1, A1, SC);                              \
            MUL2(A2, A2, SC); MUL2(A3, A3, SC);                              \
        }                                                                    \
        El = Elp;                                                            \
        int El2 = __shfl_up_sync(FULLMASK, El, 1);                           \
        int dE  = El2 - El;                                                  \
        if (lane == 0 || dE < -126) f = 0.f;                                 \
        else f = __int_as_float((min(dE, 126) + 127) << 23);                 \
    } while (0)

    // Prologue: fill ring with rows 1..DIST
    {
        const float* gp = Pb + SP;           // row 1
        #pragma unroll 4
        for (int r = 1; r <= DIST; r++) {
            unsigned int sa = rb + (unsigned int)((r & (RING - 1)) * (SP * 4));
            CP16(sa, gp); CP16(sa + 16, gp + 4);
            CP_COMMIT();
            gp += SP;
        }
    }

    ull q0 = ZERO, q1 = ZERO, q2 = ZERO, q3 = ZERO;
    if (nsteps >= 1) {
        CP_WAIT_27();                        // row 1 landed
        const ulonglong2* sp = reinterpret_cast<const ulonglong2*>(&ring[1][lane * 8]);
        ulonglong2 qa = sp[0], qb = sp[1];
        q0 = qa.x; q1 = qa.y; q2 = qb.x; q3 = qb.y;
    }

    const float* fill_ptr = Pb + (size_t)(1 + DIST) * SP;
    int t = 1;
    for (; t + 7 <= nsteps; t += 8) {
        #pragma unroll
        for (int k = 0; k < 8; k++) {
            CP_WAIT_26();                    // row t+k+1 landed
            int nslot = (t + k + 1) & (RING - 1);
            const ulonglong2* sp = reinterpret_cast<const ulonglong2*>(&ring[nslot][lane * 8]);
            ulonglong2 qa = sp[0], qb = sp[1];
            // refill: row t+k+DIST into its slot
            {
                unsigned int sa = rb +
                    (unsigned int)((((t + k + DIST) & (RING - 1))) * (SP * 4));
                const float* gp = fill_ptr + (size_t)k * SP;
                CP16(sa, gp); CP16(sa + 16, gp + 4);
                CP_COMMIT();
            }
            CTC_STEP(q0, q1, q2, q3);
            if (k == 3 || k == 7) CTC_RENORM();
            q0 = qa.x; q1 = qa.y; q2 = qb.x; q3 = qb.y;
        }
        fill_ptr += 8 * SP;
    }
    // Tail: rows t..nsteps were all prefetched into the ring (fills ran ahead
    // by DIST); wait for everything once, then consume from the ring.
    if (t <= nsteps) {
        CP_WAIT_ALL();
        for (; t <= nsteps; t++) {
            CTC_STEP(q0, q1, q2, q3);
            int nslot = (t + 1) & (RING - 1);   // content unused past nsteps
            const ulonglong2* sp = reinterpret_cast<const ulonglong2*>(&ring[nslot][lane * 8]);
            ulonglong2 qa = sp[0], qb = sp[1];
            q0 = qa.x; q1 = qa.y; q2 = qb.x; q3 = qb.y;
        }
    }
#undef CTC_STEP
#undef CTC_RENORM

    // Unpack final alpha
    float a[8];
    UNPK(a[0], a[1], A0); UNPK(a[2], a[3], A1);
    UNPK(a[4], a[5], A2); UNPK(a[6], a[7], A3);

    // end_ll over alpha[2*tl] and alpha[max(2*tl-1,0)]
    int s1 = 2 * tl;
    int s2 = (2 * tl - 1 > 0) ? (2 * tl - 1) : 0;
    int lane1 = s1 >> 3, slot1 = s1 & 7;
    int lane2 = s2 >> 3, slot2 = s2 & 7;
    float v1 = a[0], v2 = a[0];
    #pragma unroll
    for (int j = 1; j < 8; j++) { v1 = (slot1 == j) ? a[j] : v1;
                                  v2 = (slot2 == j) ? a[j] : v2; }
    int   E1 = __shfl_sync(FULLMASK, El, lane1);
    int   E2 = __shfl_sync(FULLMASK, El, lane2);
    v1 = __shfl_sync(FULLMASK, v1, lane1);
    v2 = __shfl_sync(FULLMASK, v2, lane2);

    if (lane == 0) {
        float l1 = (v1 > 0.f) ? (log2f(v1) + (float)E1) : -3.0e38f;
        float l2 = (v2 > 0.f) ? (log2f(v2) + (float)E2) : -3.0e38f;
        float mx = fmaxf(l1, l2);
        float loss;
        if (mx < -2.0e38f) {
            loss = 0.f;                    // zero_infinity: p == 0
        } else {
            float tot2 = mx + log2f(exp2f(l1 - mx) + exp2f(l2 - mx));
            loss = -tot2 * LN2_F;
        }
        g_loss[b] = loss / (float)tl;
    }
}

// ---------------------------------------------------------------------------
// Pass 3: deterministic batch-mean reduction (single warp).
// ---------------------------------------------------------------------------
__global__ void reduce_loss_kernel(float* __restrict__ out, int B)
{
    float v = 0.f;
    for (int i = threadIdx.x; i < B; i += 32) v += g_loss[i];
    #pragma unroll
    for (int o = 16; o; o >>= 1) v += __shfl_xor_sync(FULLMASK, v, o);
    if (threadIdx.x == 0) out[0] = v / (float)B;
}

// ---------------------------------------------------------------------------
extern "C" void kernel_launch(void* const* d_in, const int* in_sizes, int n_in,
                              void* d_out, int out_size)
{
    const float* pred = (const float*)d_in[0];
    const int*   plen = (const int*)d_in[1];
    const int*   gt   = (const int*)d_in[2];
    const int*   gtl  = (const int*)d_in[3];

    const int B  = in_sizes[1];
    const int L  = in_sizes[2] / B;
    const int T  = in_sizes[0] / (B * VOCAB);
    const int S  = 2 * L + 1;
    const int TP = T + 32;                // padded rows (prefetch slack)
    const int NT = B * T;

    softmax_gather_kernel<<<(NT + 7) / 8, 256>>>(pred, gt, NT, T, TP, L, S);
    ctc_forward_kernel<<<B, 32>>>(plen, gt, gtl, B, T, TP, L, S);
    reduce_loss_kernel<<<1, 32>>>((float*)d_out, B);
}